// round 15
// baseline (speedup 1.0000x reference)
#include <cuda_runtime.h>
#include <cuda_fp16.h>
#include <cuda_bf16.h>
#include <cstdint>

// Problem constants
#define BS      4
#define SEQ     2048
#define DMODEL  768
#define NHEAD   12
#define DHEAD   64
#define MROWS   (BS * SEQ)          // 8192

#define MD_ ((size_t)MROWS * DMODEL)
#define WD_ ((size_t)DMODEL * DMODEL)

// ---------------- scratch (no cudaMalloc allowed) ----------------
__device__ __nv_bfloat16 g_Ah[3 * MROWS * DMODEL];   // q,k,v inputs hi (proj A)
__device__ __nv_bfloat16 g_Al[3 * MROWS * DMODEL];   // q,k,v inputs lo
__device__ __nv_bfloat16 g_Wh[3 * DMODEL * DMODEL];  // weights hi
__device__ __nv_bfloat16 g_Wl[3 * DMODEL * DMODEL];  // weights lo
__device__ int8_t g_Qi8h[MROWS * DMODEL];            // Q 16-bit fixed: hi,lo int8
__device__ int8_t g_Qi8l[MROWS * DMODEL];
__device__ int8_t g_Ki8h[MROWS * DMODEL];
__device__ int8_t g_Ki8l[MROWS * DMODEL];
__device__ __half g_Vv[MROWS * DMODEL];              // V fp16

// =================================================================
// low-level helpers (family-common PTX: sm_80+ mma/ldmatrix/cp.async)
// =================================================================
__device__ __forceinline__ uint32_t cvta_s(const void* p) {
    return (uint32_t)__cvta_generic_to_shared(p);
}
__device__ __forceinline__ void cp16(uint32_t saddr, const void* gptr) {
    asm volatile("cp.async.ca.shared.global [%0], [%1], 16;" :: "r"(saddr), "l"(gptr));
}
#define CP_COMMIT() asm volatile("cp.async.commit_group;" ::: "memory")
#define CP_WAIT0()  asm volatile("cp.async.wait_group 0;" ::: "memory")
#define CP_WAIT1()  asm volatile("cp.async.wait_group 1;" ::: "memory")

__device__ __forceinline__ void ldm_x4(uint32_t* r, uint32_t saddr) {
    asm volatile("ldmatrix.sync.aligned.m8n8.x4.shared.b16 {%0,%1,%2,%3}, [%4];"
        : "=r"(r[0]), "=r"(r[1]), "=r"(r[2]), "=r"(r[3]) : "r"(saddr));
}
__device__ __forceinline__ void ldm_x4t(uint32_t* r, uint32_t saddr) {
    asm volatile("ldmatrix.sync.aligned.m8n8.x4.trans.shared.b16 {%0,%1,%2,%3}, [%4];"
        : "=r"(r[0]), "=r"(r[1]), "=r"(r[2]), "=r"(r[3]) : "r"(saddr));
}
__device__ __forceinline__ void mma_bf16(float* c, const uint32_t* a, uint32_t b0, uint32_t b1) {
    asm volatile(
        "mma.sync.aligned.m16n8k16.row.col.f32.bf16.bf16.f32 "
        "{%0,%1,%2,%3},{%4,%5,%6,%7},{%8,%9},{%0,%1,%2,%3};"
        : "+f"(c[0]), "+f"(c[1]), "+f"(c[2]), "+f"(c[3])
        : "r"(a[0]), "r"(a[1]), "r"(a[2]), "r"(a[3]), "r"(b0), "r"(b1));
}
__device__ __forceinline__ void mma_f16(float* c, const uint32_t* a, uint32_t b0, uint32_t b1) {
    asm volatile(
        "mma.sync.aligned.m16n8k16.row.col.f32.f16.f16.f32 "
        "{%0,%1,%2,%3},{%4,%5,%6,%7},{%8,%9},{%0,%1,%2,%3};"
        : "+f"(c[0]), "+f"(c[1]), "+f"(c[2]), "+f"(c[3])
        : "r"(a[0]), "r"(a[1]), "r"(a[2]), "r"(a[3]), "r"(b0), "r"(b1));
}
__device__ __forceinline__ void imma(int* c, const uint32_t* a, uint32_t b0, uint32_t b1) {
    asm volatile(
        "mma.sync.aligned.m16n8k32.row.col.s32.s8.s8.s32 "
        "{%0,%1,%2,%3},{%4,%5,%6,%7},{%8,%9},{%0,%1,%2,%3};"
        : "+r"(c[0]), "+r"(c[1]), "+r"(c[2]), "+r"(c[3])
        : "r"(a[0]), "r"(a[1]), "r"(a[2]), "r"(a[3]), "r"(b0), "r"(b1));
}
__device__ __forceinline__ uint32_t pk2(float x, float y) {
    __half2 h = __floats2half2_rn(x, y);
    return *(uint32_t*)&h;
}

// =================================================================
// fp32 -> (hi, lo) bf16 split; grid.z selects among 3 tensors
// =================================================================
__global__ __launch_bounds__(256) void split3_bf16(
    const float* __restrict__ s0, const float* __restrict__ s1,
    const float* __restrict__ s2, __nv_bfloat16* __restrict__ hi,
    __nv_bfloat16* __restrict__ lo, size_t stride, int n4)
{
    int i = blockIdx.x * blockDim.x + threadIdx.x;
    if (i >= n4) return;
    const int z = blockIdx.z;
    const float* src = (z == 0) ? s0 : (z == 1) ? s1 : s2;
    hi += (size_t)z * stride;
    lo += (size_t)z * stride;
    float4 x = ((const float4*)src)[i];
    __nv_bfloat16 h0 = __float2bfloat16(x.x);
    __nv_bfloat16 h1 = __float2bfloat16(x.y);
    __nv_bfloat16 h2 = __float2bfloat16(x.z);
    __nv_bfloat16 h3 = __float2bfloat16(x.w);
    __nv_bfloat16 l0 = __float2bfloat16(x.x - __bfloat162float(h0));
    __nv_bfloat16 l1 = __float2bfloat16(x.y - __bfloat162float(h1));
    __nv_bfloat16 l2 = __float2bfloat16(x.z - __bfloat162float(h2));
    __nv_bfloat16 l3 = __float2bfloat16(x.w - __bfloat162float(h3));
    __nv_bfloat162* hp = (__nv_bfloat162*)hi;
    __nv_bfloat162* lp = (__nv_bfloat162*)lo;
    hp[2 * i]     = __halves2bfloat162(h0, h1);
    hp[2 * i + 1] = __halves2bfloat162(h2, h3);
    lp[2 * i]     = __halves2bfloat162(l0, l1);
    lp[2 * i + 1] = __halves2bfloat162(l2, l3);
}

// =================================================================
// Projection GEMM (mma.sync, split-bf16 3-term), ALL THREE GEMMs in
// ONE launch. CTA 128x128, K-chunk 64, single-buffered, 2 CTAs/SM.
// Epilogue: Q/K -> 16-bit fixed point (int8 hi/lo, scale 4096);
//           V   -> fp16.
// =================================================================
#define PJ_STRIDE_B 144                      // 72 halves
#define PJ_TILE_B   (128 * PJ_STRIDE_B)      // 18432
#define PJ_SMEM     (4 * PJ_TILE_B)          // 73728

__global__ __launch_bounds__(256, 2) void proj_mma(
    const float* __restrict__ bq, const float* __restrict__ bk,
    const float* __restrict__ bv)
{
    extern __shared__ __align__(16) char sm[];

    const int z = blockIdx.z;
    const __nv_bfloat16* __restrict__ Xh = g_Ah + (size_t)z * MD_;
    const __nv_bfloat16* __restrict__ Xl = g_Al + (size_t)z * MD_;
    const __nv_bfloat16* __restrict__ Wh = g_Wh + (size_t)z * WD_;
    const __nv_bfloat16* __restrict__ Wl = g_Wl + (size_t)z * WD_;
    const float* __restrict__ bias = (z == 0) ? bq : (z == 1) ? bk : bv;

    const int K = DMODEL;
    const int tid  = threadIdx.x;
    const int wid  = tid >> 5;
    const int lane = tid & 31;
    const int m0 = blockIdx.y * 128;
    const int n0 = blockIdx.x * 128;
    const int wm = (wid >> 2) * 64;
    const int wn = (wid & 3) * 32;
    const int qr = lane >> 2;
    const int qc = (lane & 3) * 2;
    const int fr = (lane & 7) + 8 * ((lane >> 3) & 1);
    const int fc = 8 * ((lane >> 4) & 1);

    char* smAh = sm;
    char* smAl = sm + PJ_TILE_B;
    char* smBh = sm + 2 * PJ_TILE_B;
    char* smBl = sm + 3 * PJ_TILE_B;

    float acc[4][4][4];
#pragma unroll
    for (int i = 0; i < 4; i++)
#pragma unroll
        for (int j = 0; j < 4; j++)
#pragma unroll
            for (int r = 0; r < 4; r++) acc[i][j][r] = 0.0f;

    for (int c = 0; c < 12; c++) {
        const int k0 = c * 64;
#pragma unroll
        for (int it = 0; it < 4; it++) {
            int idx = it * 256 + tid;
            int row = idx >> 3;
            int c8  = idx & 7;
            uint32_t soff = row * PJ_STRIDE_B + c8 * 16;
            size_t goff = (size_t)(m0 + row) * K + k0 + c8 * 8;
            size_t woff = (size_t)(n0 + row) * K + k0 + c8 * 8;
            cp16(cvta_s(smAh + soff), &Xh[goff]);
            cp16(cvta_s(smAl + soff), &Xl[goff]);
            cp16(cvta_s(smBh + soff), &Wh[woff]);
            cp16(cvta_s(smBl + soff), &Wl[woff]);
        }
        CP_COMMIT();
        CP_WAIT0();
        __syncthreads();

#pragma unroll
        for (int ks = 0; ks < 4; ks++) {
            const int kbyte = (ks * 16 + fc) * 2;
            uint32_t ah[4][4], al[4][4], bh[2][4], bl[2][4];
#pragma unroll
            for (int i = 0; i < 4; i++) {
                uint32_t ro = (wm + i * 16 + fr) * PJ_STRIDE_B + kbyte;
                ldm_x4(ah[i], cvta_s(smAh + ro));
                ldm_x4(al[i], cvta_s(smAl + ro));
            }
#pragma unroll
            for (int j2 = 0; j2 < 2; j2++) {
                uint32_t ro = (wn + j2 * 16 + fr) * PJ_STRIDE_B + kbyte;
                ldm_x4(bh[j2], cvta_s(smBh + ro));
                ldm_x4(bl[j2], cvta_s(smBl + ro));
            }
#pragma unroll
            for (int i = 0; i < 4; i++)
#pragma unroll
                for (int j = 0; j < 4; j++)
                    mma_bf16(acc[i][j], ah[i], bh[j >> 1][j & 1], bh[j >> 1][(j & 1) + 2]);
#pragma unroll
            for (int i = 0; i < 4; i++)
#pragma unroll
                for (int j = 0; j < 4; j++)
                    mma_bf16(acc[i][j], ah[i], bl[j >> 1][j & 1], bl[j >> 1][(j & 1) + 2]);
#pragma unroll
            for (int i = 0; i < 4; i++)
#pragma unroll
                for (int j = 0; j < 4; j++)
                    mma_bf16(acc[i][j], al[i], bh[j >> 1][j & 1], bh[j >> 1][(j & 1) + 2]);
        }
        __syncthreads();
    }

    // ---- epilogue ----
    if (z == 2) {
        // V: fp16
#pragma unroll
        for (int j = 0; j < 4; j++) {
            int gc = n0 + wn + j * 8 + qc;
            float b0 = __ldg(&bias[gc]);
            float b1 = __ldg(&bias[gc + 1]);
#pragma unroll
            for (int i = 0; i < 4; i++) {
                int gr = m0 + wm + i * 16 + qr;
                __half h0 = __float2half_rn(acc[i][j][0] + b0);
                __half h1 = __float2half_rn(acc[i][j][1] + b1);
                __half h2 = __float2half_rn(acc[i][j][2] + b0);
                __half h3 = __float2half_rn(acc[i][j][3] + b1);
                *(__half2*)&g_Vv[(size_t)gr * DMODEL + gc]       = __halves2half2(h0, h1);
                *(__half2*)&g_Vv[(size_t)(gr + 8) * DMODEL + gc] = __halves2half2(h2, h3);
            }
        }
    } else {
        // Q/K: 16-bit fixed point, scale 4096, split into int8 hi/lo
        int8_t* __restrict__ OH = (z == 0) ? g_Qi8h : g_Ki8h;
        int8_t* __restrict__ OL = (z == 0) ? g_Qi8l : g_Ki8l;
#pragma unroll
        for (int j = 0; j < 4; j++) {
            int gc = n0 + wn + j * 8 + qc;
            float b0 = __ldg(&bias[gc]);
            float b1 = __ldg(&bias[gc + 1]);
#pragma unroll
            for (int i = 0; i < 4; i++) {
                int gr = m0 + wm + i * 16 + qr;
                int v[4];
                v[0] = __float2int_rn((acc[i][j][0] + b0) * 4096.0f);
                v[1] = __float2int_rn((acc[i][j][1] + b1) * 4096.0f);
                v[2] = __float2int_rn((acc[i][j][2] + b0) * 4096.0f);
                v[3] = __float2int_rn((acc[i][j][3] + b1) * 4096.0f);
                int hi[4], lo[4];
#pragma unroll
                for (int r = 0; r < 4; r++) {
                    int t = min(32639, max(-32767, v[r]));
                    hi[r] = (t + 128) >> 8;
                    lo[r] = t - (hi[r] << 8);
                }
                char2 h01 = make_char2((char)hi[0], (char)hi[1]);
                char2 h23 = make_char2((char)hi[2], (char)hi[3]);
                char2 l01 = make_char2((char)lo[0], (char)lo[1]);
                char2 l23 = make_char2((char)lo[2], (char)lo[3]);
                *(char2*)&OH[(size_t)gr * DMODEL + gc]       = h01;
                *(char2*)&OH[(size_t)(gr + 8) * DMODEL + gc] = h23;
                *(char2*)&OL[(size_t)gr * DMODEL + gc]       = l01;
                *(char2*)&OL[(size_t)(gr + 8) * DMODEL + gc] = l23;
            }
        }
    }
}

// =================================================================
// Flash attention: int8 IMMA QK^T (exact 16-bit fixed point, 4 terms
// in 3 s32 accumulator sets), fp16 PV. 8 warps x 16 q-rows, BK=64,
// double-buffered KV, 1 CTA/SM. Softmax in log2 domain (folded into
// the dequant constant), lazy O-rescale.
// =================================================================
#define QI_STR 80
#define KI_STR 80
#define QI_TILE (128 * QI_STR)               // 10240
#define KI_TILE (64 * KI_STR)                // 5120
#define VROW 72                              // halves
#define V_TILE_B (64 * VROW * 2)             // 9216
#define KVBUF (2 * KI_TILE + V_TILE_B)       // 19456
#define FI_SMEM (2 * QI_TILE + 2 * KVBUF)    // 59392

__global__ __launch_bounds__(256, 1) void flash_i8(
    const int8_t* __restrict__ Qh8, const int8_t* __restrict__ Ql8,
    const int8_t* __restrict__ Kh8, const int8_t* __restrict__ Kl8,
    const __half* __restrict__ Vv, float* __restrict__ Out)
{
    extern __shared__ __align__(16) char smc[];
    char* sQh = smc;
    char* sQl = smc + QI_TILE;
    char* sKV = smc + 2 * QI_TILE;

    const int qt  = blockIdx.x;
    const int h   = blockIdx.y;
    const int b   = blockIdx.z;
    const int tid  = threadIdx.x;
    const int w    = tid >> 5;
    const int lane = tid & 31;

    // dequant constants: S_log2 = (A*65536 + B*256 + C) * log2e / 4096^2
    const float C3 = 1.4426950408889634f / 16777216.0f;
    const float C1 = C3 * 65536.0f;
    const float C2 = C3 * 256.0f;

    const size_t qbase = ((size_t)(b * SEQ + qt * 128)) * DMODEL + h * DHEAD;

    // ---- async-load Q int8 tiles (hi, lo): 128 rows x 4 x 16B ----
#pragma unroll
    for (int it = 0; it < 2; it++) {
        int idx = it * 256 + tid;
        int row = idx >> 2;
        int c4  = idx & 3;
        uint32_t soff = row * QI_STR + c4 * 16;
        size_t goff = qbase + (size_t)row * DMODEL + c4 * 16;
        cp16(cvta_s(sQh + soff), &Qh8[goff]);
        cp16(cvta_s(sQl + soff), &Ql8[goff]);
    }
    CP_COMMIT();

    auto load_kv = [&](int kt, int buf) {
        char* base = sKV + buf * KVBUF;
        size_t kbase = ((size_t)(b * SEQ + kt * 64)) * DMODEL + h * DHEAD;
        // K hi/lo: 64 rows x 4 x 16B  (256 slots = 1 per thread)
        {
            int row = tid >> 2;
            int c4  = tid & 3;
            uint32_t soff = row * KI_STR + c4 * 16;
            size_t goff = kbase + (size_t)row * DMODEL + c4 * 16;
            cp16(cvta_s(base + soff),           &Kh8[goff]);
            cp16(cvta_s(base + KI_TILE + soff), &Kl8[goff]);
        }
        // V fp16: 64 rows x 8 x 16B
        __half* vb = (__half*)(base + 2 * KI_TILE);
#pragma unroll
        for (int it = 0; it < 2; it++) {
            int idx = it * 256 + tid;
            int row = idx >> 3;
            int c8  = idx & 7;
            uint32_t soff = row * VROW + c8 * 8;   // halves
            size_t goff = kbase + (size_t)row * DMODEL + c8 * 8;
            cp16(cvta_s(vb + soff), &Vv[goff]);
        }
    };

    load_kv(0, 0);
    CP_COMMIT();

    CP_WAIT1();
    __syncthreads();

    const int fr  = (lane & 7) + 8 * ((lane >> 3) & 1);
    const int fcb = 16 * ((lane >> 4) & 1);            // byte offset

    uint32_t qhF[2][4], qlF[2][4];
    {
        int qrow = 16 * w + fr;
#pragma unroll
        for (int kc = 0; kc < 2; kc++) {
            ldm_x4(qhF[kc], cvta_s(sQh + qrow * QI_STR + kc * 32 + fcb));
            ldm_x4(qlF[kc], cvta_s(sQl + qrow * QI_STR + kc * 32 + fcb));
        }
    }

    float m0 = -1e30f, m1 = -1e30f, l0 = 0.0f, l1 = 0.0f;
    float O[8][4];
#pragma unroll
    for (int dt = 0; dt < 8; dt++)
#pragma unroll
        for (int r = 0; r < 4; r++) O[dt][r] = 0.0f;

#pragma unroll 1
    for (int kt = 0; kt < SEQ / 64; kt++) {
        if (kt + 1 < SEQ / 64) { load_kv(kt + 1, (kt + 1) & 1); CP_COMMIT(); }
        if (kt + 1 < SEQ / 64) CP_WAIT1(); else CP_WAIT0();
        __syncthreads();

        char* base = sKV + (kt & 1) * KVBUF;
        char* bKh = base;
        char* bKl = base + KI_TILE;
        __half* bV = (__half*)(base + 2 * KI_TILE);

        // ---- QK^T: exact 16-bit fixed point, 3 s32 acc sets ----
        int A[8][4], B[8][4], Cc[8][4];
#pragma unroll
        for (int nt = 0; nt < 8; nt++)
#pragma unroll
            for (int r = 0; r < 4; r++) { A[nt][r] = 0; B[nt][r] = 0; Cc[nt][r] = 0; }

#pragma unroll
        for (int kc = 0; kc < 2; kc++) {
            uint32_t kh[4][4], kl[4][4];
#pragma unroll
            for (int nt2 = 0; nt2 < 4; nt2++) {
                uint32_t ro = (nt2 * 16 + fr) * KI_STR + kc * 32 + fcb;
                ldm_x4(kh[nt2], cvta_s(bKh + ro));
                ldm_x4(kl[nt2], cvta_s(bKl + ro));
            }
            // hh -> A
#pragma unroll
            for (int nt2 = 0; nt2 < 4; nt2++) {
                imma(A[2 * nt2],     qhF[kc], kh[nt2][0], kh[nt2][2]);
                imma(A[2 * nt2 + 1], qhF[kc], kh[nt2][1], kh[nt2][3]);
            }
            // hl -> B
#pragma unroll
            for (int nt2 = 0; nt2 < 4; nt2++) {
                imma(B[2 * nt2],     qhF[kc], kl[nt2][0], kl[nt2][2]);
                imma(B[2 * nt2 + 1], qhF[kc], kl[nt2][1], kl[nt2][3]);
            }
            // lh -> B
#pragma unroll
            for (int nt2 = 0; nt2 < 4; nt2++) {
                imma(B[2 * nt2],     qlF[kc], kh[nt2][0], kh[nt2][2]);
                imma(B[2 * nt2 + 1], qlF[kc], kh[nt2][1], kh[nt2][3]);
            }
            // ll -> C
#pragma unroll
            for (int nt2 = 0; nt2 < 4; nt2++) {
                imma(Cc[2 * nt2],     qlF[kc], kl[nt2][0], kl[nt2][2]);
                imma(Cc[2 * nt2 + 1], qlF[kc], kl[nt2][1], kl[nt2][3]);
            }
        }

        // ---- dequant to log2-domain scores ----
        float S[8][4];
#pragma unroll
        for (int nt = 0; nt < 8; nt++)
#pragma unroll
            for (int r = 0; r < 4; r++)
                S[nt][r] = fmaf(__int2float_rn(A[nt][r]), C1,
                            fmaf(__int2float_rn(B[nt][r]), C2,
                                 __int2float_rn(Cc[nt][r]) * C3));

        // ---- online softmax (log2 domain, lazy rescale) ----
        float mx0 = S[0][0], mx1 = S[0][2];
#pragma unroll
        for (int nt = 0; nt < 8; nt++) {
            mx0 = fmaxf(mx0, fmaxf(S[nt][0], S[nt][1]));
            mx1 = fmaxf(mx1, fmaxf(S[nt][2], S[nt][3]));
        }
        mx0 = fmaxf(mx0, __shfl_xor_sync(0xffffffffu, mx0, 1));
        mx0 = fmaxf(mx0, __shfl_xor_sync(0xffffffffu, mx0, 2));
        mx1 = fmaxf(mx1, __shfl_xor_sync(0xffffffffu, mx1, 1));
        mx1 = fmaxf(mx1, __shfl_xor_sync(0xffffffffu, mx1, 2));
        float mn0 = fmaxf(m0, mx0), mn1 = fmaxf(m1, mx1);
        bool up0 = mn0 > m0, up1 = mn1 > m1;
        float c0 = up0 ? exp2f(m0 - mn0) : 1.0f;
        float c1 = up1 ? exp2f(m1 - mn1) : 1.0f;
        float s0 = 0.0f, s1 = 0.0f;
#pragma unroll
        for (int nt = 0; nt < 8; nt++) {
            S[nt][0] = exp2f(S[nt][0] - mn0); s0 += S[nt][0];
            S[nt][1] = exp2f(S[nt][1] - mn0); s0 += S[nt][1];
            S[nt][2] = exp2f(S[nt][2] - mn1); s1 += S[nt][2];
            S[nt][3] = exp2f(S[nt][3] - mn1); s1 += S[nt][3];
        }
        s0 += __shfl_xor_sync(0xffffffffu, s0, 1);
        s0 += __shfl_xor_sync(0xffffffffu, s0, 2);
        s1 += __shfl_xor_sync(0xffffffffu, s1, 1);
        s1 += __shfl_xor_sync(0xffffffffu, s1, 2);
        l0 = l0 * c0 + s0; l1 = l1 * c1 + s1;
        m0 = mn0; m1 = mn1;
        if (up0 || up1) {
#pragma unroll
            for (int dt = 0; dt < 8; dt++) {
                O[dt][0] *= c0; O[dt][1] *= c0;
                O[dt][2] *= c1; O[dt][3] *= c1;
            }
        }

        // ---- O += P.V : fp16, 4 k-chunks of 16 keys ----
#pragma unroll
        for (int kc = 0; kc < 4; kc++) {
            uint32_t a[4];
            a[0] = pk2(S[2 * kc][0],     S[2 * kc][1]);
            a[1] = pk2(S[2 * kc][2],     S[2 * kc][3]);
            a[2] = pk2(S[2 * kc + 1][0], S[2 * kc + 1][1]);
            a[3] = pk2(S[2 * kc + 1][2], S[2 * kc + 1][3]);
            int vrow = kc * 16 + fr;
#pragma unroll
            for (int dt2 = 0; dt2 < 4; dt2++) {
                uint32_t r[4];
                ldm_x4t(r, cvta_s(bV + vrow * VROW + dt2 * 16 + (fcb >> 1)));
                mma_f16(O[2 * dt2],     a, r[0], r[1]);
                mma_f16(O[2 * dt2 + 1], a, r[2], r[3]);
            }
        }
        __syncthreads();
    }

    // ---- write output ----
    float il0 = 1.0f / l0, il1 = 1.0f / l1;
    int row0 = b * SEQ + qt * 128 + 16 * w + (lane >> 2);
    int dcol = h * DHEAD + 2 * (lane & 3);
#pragma unroll
    for (int dt = 0; dt < 8; dt++) {
        *(float2*)&Out[(size_t)row0 * DMODEL + dcol + dt * 8] =
            make_float2(O[dt][0] * il0, O[dt][1] * il0);
        *(float2*)&Out[(size_t)(row0 + 8) * DMODEL + dcol + dt * 8] =
            make_float2(O[dt][2] * il1, O[dt][3] * il1);
    }
}

// =================================================================
extern "C" void kernel_launch(void* const* d_in, const int* in_sizes, int n_in,
                              void* d_out, int out_size)
{
    const float* q  = (const float*)d_in[0];
    const float* k  = (const float*)d_in[1];
    const float* v  = (const float*)d_in[2];
    const float* Wq = (const float*)d_in[3];
    const float* bq = (const float*)d_in[4];
    const float* Wk = (const float*)d_in[5];
    const float* bk = (const float*)d_in[6];
    const float* Wv = (const float*)d_in[7];
    const float* bv = (const float*)d_in[8];
    float* out = (float*)d_out;

    __nv_bfloat16 *Ah, *Al, *Wh, *Wl;
    int8_t *Qh8, *Ql8, *Kh8, *Kl8;
    __half *Vv;
    cudaGetSymbolAddress((void**)&Ah, g_Ah);
    cudaGetSymbolAddress((void**)&Al, g_Al);
    cudaGetSymbolAddress((void**)&Wh, g_Wh);
    cudaGetSymbolAddress((void**)&Wl, g_Wl);
    cudaGetSymbolAddress((void**)&Qh8, g_Qi8h);
    cudaGetSymbolAddress((void**)&Ql8, g_Qi8l);
    cudaGetSymbolAddress((void**)&Kh8, g_Ki8h);
    cudaGetSymbolAddress((void**)&Kl8, g_Ki8l);
    cudaGetSymbolAddress((void**)&Vv, g_Vv);

    const size_t MD = MD_;
    const size_t WD = WD_;
    const int n4i = (int)(MD / 4);
    const int n4w = (int)(WD / 4);

    {
        dim3 gi((n4i + 255) / 256, 1, 3);
        split3_bf16<<<gi, 256>>>(q, k, v, Ah, Al, MD, n4i);
        dim3 gw((n4w + 255) / 256, 1, 3);
        split3_bf16<<<gw, 256>>>(Wq, Wk, Wv, Wh, Wl, WD, n4w);
    }

    cudaFuncSetAttribute(proj_mma, cudaFuncAttributeMaxDynamicSharedMemorySize, PJ_SMEM);
    cudaFuncSetAttribute(flash_i8, cudaFuncAttributeMaxDynamicSharedMemorySize, FI_SMEM);

    dim3 pgrid(DMODEL / 128, MROWS / 128, 3);   // (6, 64, 3) — all 3 GEMMs
    proj_mma<<<pgrid, 256, PJ_SMEM>>>(bq, bk, bv);

    dim3 agrid(SEQ / 128, NHEAD, BS);           // (16, 12, 4)
    flash_i8<<<agrid, 256, FI_SMEM>>>(Qh8, Ql8, Kh8, Kl8, Vv, out);
}

// round 16
// speedup vs baseline: 2.2110x; 2.2110x over previous
#include <cuda_runtime.h>
#include <cuda_fp16.h>
#include <cuda_bf16.h>
#include <cstdint>

// Problem constants
#define BS      4
#define SEQ     2048
#define DMODEL  768
#define NHEAD   12
#define DHEAD   64
#define MROWS   (BS * SEQ)          // 8192

#define MD_ ((size_t)MROWS * DMODEL)
#define WD_ ((size_t)DMODEL * DMODEL)

// ---------------- scratch (no cudaMalloc allowed) ----------------
__device__ __nv_bfloat16 g_Ah[3 * MROWS * DMODEL];   // q,k,v inputs hi (proj A)
__device__ __nv_bfloat16 g_Al[3 * MROWS * DMODEL];   // q,k,v inputs lo
__device__ __nv_bfloat16 g_Wh[3 * DMODEL * DMODEL];  // weights hi
__device__ __nv_bfloat16 g_Wl[3 * DMODEL * DMODEL];  // weights lo
__device__ __half g_Qh[MROWS * DMODEL];              // proj outputs, fp16
__device__ __half g_Ql[MROWS * DMODEL];              // (Q pre-scaled by log2e)
__device__ __half g_Kh[MROWS * DMODEL];
__device__ __half g_Kl[MROWS * DMODEL];
__device__ __half g_Vv[MROWS * DMODEL];

// =================================================================
// low-level helpers (family-common PTX: sm_80+ mma/ldmatrix/cp.async)
// =================================================================
__device__ __forceinline__ uint32_t cvta_s(const void* p) {
    return (uint32_t)__cvta_generic_to_shared(p);
}
__device__ __forceinline__ void cp16(uint32_t saddr, const void* gptr) {
    asm volatile("cp.async.ca.shared.global [%0], [%1], 16;" :: "r"(saddr), "l"(gptr));
}
#define CP_COMMIT() asm volatile("cp.async.commit_group;" ::: "memory")
#define CP_WAIT0()  asm volatile("cp.async.wait_group 0;" ::: "memory")
#define CP_WAIT1()  asm volatile("cp.async.wait_group 1;" ::: "memory")

__device__ __forceinline__ void ldm_x4(uint32_t* r, uint32_t saddr) {
    asm volatile("ldmatrix.sync.aligned.m8n8.x4.shared.b16 {%0,%1,%2,%3}, [%4];"
        : "=r"(r[0]), "=r"(r[1]), "=r"(r[2]), "=r"(r[3]) : "r"(saddr));
}
__device__ __forceinline__ void ldm_x4t(uint32_t* r, uint32_t saddr) {
    asm volatile("ldmatrix.sync.aligned.m8n8.x4.trans.shared.b16 {%0,%1,%2,%3}, [%4];"
        : "=r"(r[0]), "=r"(r[1]), "=r"(r[2]), "=r"(r[3]) : "r"(saddr));
}
__device__ __forceinline__ void mma_bf16(float* c, const uint32_t* a, uint32_t b0, uint32_t b1) {
    asm volatile(
        "mma.sync.aligned.m16n8k16.row.col.f32.bf16.bf16.f32 "
        "{%0,%1,%2,%3},{%4,%5,%6,%7},{%8,%9},{%0,%1,%2,%3};"
        : "+f"(c[0]), "+f"(c[1]), "+f"(c[2]), "+f"(c[3])
        : "r"(a[0]), "r"(a[1]), "r"(a[2]), "r"(a[3]), "r"(b0), "r"(b1));
}
__device__ __forceinline__ void mma_f16(float* c, const uint32_t* a, uint32_t b0, uint32_t b1) {
    asm volatile(
        "mma.sync.aligned.m16n8k16.row.col.f32.f16.f16.f32 "
        "{%0,%1,%2,%3},{%4,%5,%6,%7},{%8,%9},{%0,%1,%2,%3};"
        : "+f"(c[0]), "+f"(c[1]), "+f"(c[2]), "+f"(c[3])
        : "r"(a[0]), "r"(a[1]), "r"(a[2]), "r"(a[3]), "r"(b0), "r"(b1));
}
__device__ __forceinline__ uint32_t pk2(float x, float y) {
    __half2 h = __floats2half2_rn(x, y);
    return *(uint32_t*)&h;
}

// =================================================================
// fp32 -> (hi, lo) bf16 split: ONE launch covering all 6 tensors
// (3 inputs of n4i float4s, then 3 weights of n4w float4s), flat idx.
// =================================================================
__global__ __launch_bounds__(256) void split6_bf16(
    const float* __restrict__ x0, const float* __restrict__ x1,
    const float* __restrict__ x2, const float* __restrict__ w0,
    const float* __restrict__ w1, const float* __restrict__ w2,
    int n4i, int n4w)
{
    long long g = (long long)blockIdx.x * blockDim.x + threadIdx.x;
    const long long tot_i = 3LL * n4i;
    const float* src;
    __nv_bfloat16 *hi, *lo;
    int i;
    if (g < tot_i) {
        int z = (int)(g / n4i);
        i = (int)(g - (long long)z * n4i);
        src = (z == 0) ? x0 : (z == 1) ? x1 : x2;
        hi = g_Ah + (size_t)z * MD_;
        lo = g_Al + (size_t)z * MD_;
    } else {
        long long gw = g - tot_i;
        if (gw >= 3LL * n4w) return;
        int z = (int)(gw / n4w);
        i = (int)(gw - (long long)z * n4w);
        src = (z == 0) ? w0 : (z == 1) ? w1 : w2;
        hi = g_Wh + (size_t)z * WD_;
        lo = g_Wl + (size_t)z * WD_;
    }
    float4 x = ((const float4*)src)[i];
    __nv_bfloat16 h0 = __float2bfloat16(x.x);
    __nv_bfloat16 h1 = __float2bfloat16(x.y);
    __nv_bfloat16 h2 = __float2bfloat16(x.z);
    __nv_bfloat16 h3 = __float2bfloat16(x.w);
    __nv_bfloat16 l0 = __float2bfloat16(x.x - __bfloat162float(h0));
    __nv_bfloat16 l1 = __float2bfloat16(x.y - __bfloat162float(h1));
    __nv_bfloat16 l2 = __float2bfloat16(x.z - __bfloat162float(h2));
    __nv_bfloat16 l3 = __float2bfloat16(x.w - __bfloat162float(h3));
    __nv_bfloat162* hp = (__nv_bfloat162*)hi;
    __nv_bfloat162* lp = (__nv_bfloat162*)lo;
    hp[2 * i]     = __halves2bfloat162(h0, h1);
    hp[2 * i + 1] = __halves2bfloat162(h2, h3);
    lp[2 * i]     = __halves2bfloat162(l0, l1);
    lp[2 * i + 1] = __halves2bfloat162(l2, l3);
}

// =================================================================
// Projection GEMM (mma.sync, split-bf16 3-term), ALL THREE GEMMs in
// ONE launch (grid.z selects q/k/v) for wave packing.
// CTA 128x128, K-chunk 64, single-buffered smem (73.7KB), 2 CTAs/SM.
// Q output (z==0) is pre-scaled by log2(e) for exp2-domain softmax.
// =================================================================
#define PJ_STRIDE_B 144                      // 72 halves
#define PJ_TILE_B   (128 * PJ_STRIDE_B)      // 18432
#define PJ_SMEM     (4 * PJ_TILE_B)          // 73728 (1 buffer x 4 tiles)

__global__ __launch_bounds__(256, 2) void proj_mma(
    const float* __restrict__ bq, const float* __restrict__ bk,
    const float* __restrict__ bv)
{
    extern __shared__ __align__(16) char sm[];

    const int z = blockIdx.z;
    const __nv_bfloat16* __restrict__ Xh = g_Ah + (size_t)z * MD_;
    const __nv_bfloat16* __restrict__ Xl = g_Al + (size_t)z * MD_;
    const __nv_bfloat16* __restrict__ Wh = g_Wh + (size_t)z * WD_;
    const __nv_bfloat16* __restrict__ Wl = g_Wl + (size_t)z * WD_;
    const float* __restrict__ bias = (z == 0) ? bq : (z == 1) ? bk : bv;
    __half* __restrict__ Oh = (z == 0) ? g_Qh : (z == 1) ? g_Kh : g_Vv;
    __half* __restrict__ Ol = (z == 0) ? g_Ql : g_Kl;
    const int write_lo = (z < 2);
    const float oscale = (z == 0) ? 1.4426950408889634f : 1.0f;

    const int K = DMODEL;
    const int tid  = threadIdx.x;
    const int wid  = tid >> 5;
    const int lane = tid & 31;
    const int m0 = blockIdx.y * 128;
    const int n0 = blockIdx.x * 128;
    const int wm = (wid >> 2) * 64;
    const int wn = (wid & 3) * 32;
    const int qr = lane >> 2;
    const int qc = (lane & 3) * 2;
    const int fr = (lane & 7) + 8 * ((lane >> 3) & 1);   // ldmatrix row
    const int fc = 8 * ((lane >> 4) & 1);                // ldmatrix col (halves)

    char* smAh = sm;
    char* smAl = sm + PJ_TILE_B;
    char* smBh = sm + 2 * PJ_TILE_B;
    char* smBl = sm + 3 * PJ_TILE_B;

    float acc[4][4][4];
#pragma unroll
    for (int i = 0; i < 4; i++)
#pragma unroll
        for (int j = 0; j < 4; j++)
#pragma unroll
            for (int r = 0; r < 4; r++) acc[i][j][r] = 0.0f;

    for (int c = 0; c < 12; c++) {
        const int k0 = c * 64;
        // ---- async load chunk into the single buffer ----
#pragma unroll
        for (int it = 0; it < 4; it++) {
            int idx = it * 256 + tid;
            int row = idx >> 3;
            int c8  = idx & 7;
            uint32_t soff = row * PJ_STRIDE_B + c8 * 16;
            size_t goff = (size_t)(m0 + row) * K + k0 + c8 * 8;
            size_t woff = (size_t)(n0 + row) * K + k0 + c8 * 8;
            cp16(cvta_s(smAh + soff), &Xh[goff]);
            cp16(cvta_s(smAl + soff), &Xl[goff]);
            cp16(cvta_s(smBh + soff), &Wh[woff]);
            cp16(cvta_s(smBl + soff), &Wl[woff]);
        }
        CP_COMMIT();
        CP_WAIT0();
        __syncthreads();

#pragma unroll
        for (int ks = 0; ks < 4; ks++) {
            const int kbyte = (ks * 16 + fc) * 2;
            uint32_t ah[4][4], al[4][4], bh[2][4], bl[2][4];
#pragma unroll
            for (int i = 0; i < 4; i++) {
                uint32_t ro = (wm + i * 16 + fr) * PJ_STRIDE_B + kbyte;
                ldm_x4(ah[i], cvta_s(smAh + ro));
                ldm_x4(al[i], cvta_s(smAl + ro));
            }
#pragma unroll
            for (int j2 = 0; j2 < 2; j2++) {
                uint32_t ro = (wn + j2 * 16 + fr) * PJ_STRIDE_B + kbyte;
                ldm_x4(bh[j2], cvta_s(smBh + ro));
                ldm_x4(bl[j2], cvta_s(smBl + ro));
            }
#pragma unroll
            for (int i = 0; i < 4; i++)
#pragma unroll
                for (int j = 0; j < 4; j++)
                    mma_bf16(acc[i][j], ah[i], bh[j >> 1][j & 1], bh[j >> 1][(j & 1) + 2]);
#pragma unroll
            for (int i = 0; i < 4; i++)
#pragma unroll
                for (int j = 0; j < 4; j++)
                    mma_bf16(acc[i][j], ah[i], bl[j >> 1][j & 1], bl[j >> 1][(j & 1) + 2]);
#pragma unroll
            for (int i = 0; i < 4; i++)
#pragma unroll
                for (int j = 0; j < 4; j++)
                    mma_bf16(acc[i][j], al[i], bh[j >> 1][j & 1], bh[j >> 1][(j & 1) + 2]);
        }
        __syncthreads();
    }

    // ---- epilogue: bias, optional log2e scale, write fp16 hi (and lo) ----
#pragma unroll
    for (int j = 0; j < 4; j++) {
        int gc = n0 + wn + j * 8 + qc;
        float b0 = __ldg(&bias[gc]);
        float b1 = __ldg(&bias[gc + 1]);
#pragma unroll
        for (int i = 0; i < 4; i++) {
            int gr = m0 + wm + i * 16 + qr;
            float y0 = (acc[i][j][0] + b0) * oscale, y1 = (acc[i][j][1] + b1) * oscale;
            float y2 = (acc[i][j][2] + b0) * oscale, y3 = (acc[i][j][3] + b1) * oscale;
            __half h0 = __float2half_rn(y0), h1 = __float2half_rn(y1);
            __half h2 = __float2half_rn(y2), h3 = __float2half_rn(y3);
            *(__half2*)&Oh[(size_t)gr * DMODEL + gc]       = __halves2half2(h0, h1);
            *(__half2*)&Oh[(size_t)(gr + 8) * DMODEL + gc] = __halves2half2(h2, h3);
            if (write_lo) {
                __half l0 = __float2half_rn(y0 - __half2float(h0));
                __half l1 = __float2half_rn(y1 - __half2float(h1));
                __half l2 = __float2half_rn(y2 - __half2float(h2));
                __half l3 = __float2half_rn(y3 - __half2float(h3));
                *(__half2*)&Ol[(size_t)gr * DMODEL + gc]       = __halves2half2(l0, l1);
                *(__half2*)&Ol[(size_t)(gr + 8) * DMODEL + gc] = __halves2half2(l2, l3);
            }
        }
    }
}

// =================================================================
// Flash attention via mma.sync fp16 — FAT-WARP version (R14 best):
// 4 warps x 32 q-rows (2 m-tiles per warp). Each K/V fragment feeds
// 4 MMAs; per-SM LDSM traffic halves. 128 threads, 2 CTAs/SM.
// S in log2 domain (Q pre-scaled); exp2f softmax; lazy O-rescale.
// =================================================================
#define FROW   72                   // halves per smem row (144 B)
#define THALF  (128 * FROW)         // halves per 128-row Q tile
#define KHALF  (64 * FROW)          // halves per 64-row KV tile
#define FA_SMEM ((2 * THALF + 6 * KHALF) * 2)   // 92160 B

__global__ __launch_bounds__(128, 2) void flash_mma(
    const __half* __restrict__ Qh, const __half* __restrict__ Ql,
    const __half* __restrict__ Kh, const __half* __restrict__ Kl,
    const __half* __restrict__ Vv, float* __restrict__ Out)
{
    extern __shared__ __align__(16) __half smh[];
    __half* sQh = smh;
    __half* sQl = smh + THALF;
    __half* sKV = smh + 2 * THALF;   // buffers: buf*3*KHALF + {Kh,Kl,V}*KHALF

    const int qt  = blockIdx.x;
    const int h   = blockIdx.y;
    const int b   = blockIdx.z;
    const int tid  = threadIdx.x;
    const int w    = tid >> 5;       // 0..3
    const int lane = tid & 31;

    const size_t qbase = ((size_t)(b * SEQ + qt * 128)) * DMODEL + h * DHEAD;

    // ---- async-load Q tiles (hi, lo): 128 rows x 8 float4 slots ----
#pragma unroll
    for (int it = 0; it < 8; it++) {
        int idx = it * 128 + tid;
        int row = idx >> 3;
        int c8  = idx & 7;
        uint32_t soff = row * FROW + c8 * 8;
        size_t goff = qbase + (size_t)row * DMODEL + c8 * 8;
        cp16(cvta_s(sQh + soff), &Qh[goff]);
        cp16(cvta_s(sQl + soff), &Ql[goff]);
    }
    CP_COMMIT();

    auto load_kv = [&](int kt, int buf) {
        __half* base = sKV + buf * 3 * KHALF;
        size_t kbase = ((size_t)(b * SEQ + kt * 64)) * DMODEL + h * DHEAD;
#pragma unroll
        for (int it = 0; it < 4; it++) {
            int idx = it * 128 + tid;       // 0..511
            int row = idx >> 3;             // 0..63
            int c8  = idx & 7;
            uint32_t soff = row * FROW + c8 * 8;
            size_t goff = kbase + (size_t)row * DMODEL + c8 * 8;
            cp16(cvta_s(base + soff),             &Kh[goff]);
            cp16(cvta_s(base + KHALF + soff),     &Kl[goff]);
            cp16(cvta_s(base + 2 * KHALF + soff), &Vv[goff]);
        }
    };

    load_kv(0, 0);
    CP_COMMIT();

    // ---- wait for Q, read Q-hi fragments (held for whole kernel) ----
    CP_WAIT1();
    __syncthreads();

    const int fr = (lane & 7) + 8 * ((lane >> 3) & 1);   // ldmatrix row-in-16
    const int fc = 8 * ((lane >> 4) & 1);                // ldmatrix col half

    uint32_t qhF[2][4][4];
#pragma unroll
    for (int mi = 0; mi < 2; mi++) {
        int qrow = 32 * w + 16 * mi + fr;
#pragma unroll
        for (int kc = 0; kc < 4; kc++)
            ldm_x4(qhF[mi][kc], cvta_s(sQh + qrow * FROW + kc * 16 + fc));
    }

    float m_[2][2], l_[2][2];
#pragma unroll
    for (int mi = 0; mi < 2; mi++) {
        m_[mi][0] = -1e30f; m_[mi][1] = -1e30f;
        l_[mi][0] = 0.0f;   l_[mi][1] = 0.0f;
    }
    float O[2][8][4];
#pragma unroll
    for (int mi = 0; mi < 2; mi++)
#pragma unroll
        for (int dt = 0; dt < 8; dt++)
#pragma unroll
            for (int r = 0; r < 4; r++) O[mi][dt][r] = 0.0f;

#pragma unroll 1
    for (int kt = 0; kt < SEQ / 64; kt++) {
        if (kt + 1 < SEQ / 64) { load_kv(kt + 1, (kt + 1) & 1); CP_COMMIT(); }
        if (kt + 1 < SEQ / 64) CP_WAIT1(); else CP_WAIT0();
        __syncthreads();

        __half* base = sKV + (kt & 1) * 3 * KHALF;
        __half* bKh = base;
        __half* bKl = base + KHALF;
        __half* bV  = base + 2 * KHALF;

        // ---- S = Q.K^T: 2 m-tiles share each K fragment (4 MMA/LDSM) ----
        float S[2][8][4];
#pragma unroll
        for (int mi = 0; mi < 2; mi++)
#pragma unroll
            for (int nt = 0; nt < 8; nt++)
#pragma unroll
                for (int r = 0; r < 4; r++) S[mi][nt][r] = 0.0f;

#pragma unroll
        for (int kc = 0; kc < 4; kc++) {
            uint32_t bf[4][4];
#pragma unroll
            for (int nt2 = 0; nt2 < 4; nt2++)
                ldm_x4(bf[nt2], cvta_s(bKh + (nt2 * 16 + fr) * FROW + kc * 16 + fc));
            uint32_t ql2[2][4];
#pragma unroll
            for (int mi = 0; mi < 2; mi++)
                ldm_x4(ql2[mi], cvta_s(sQl + (32 * w + 16 * mi + fr) * FROW + kc * 16 + fc));
            // pass A: Qh.Kh
#pragma unroll
            for (int mi = 0; mi < 2; mi++)
#pragma unroll
                for (int nt2 = 0; nt2 < 4; nt2++) {
                    mma_f16(S[mi][2 * nt2],     qhF[mi][kc], bf[nt2][0], bf[nt2][2]);
                    mma_f16(S[mi][2 * nt2 + 1], qhF[mi][kc], bf[nt2][1], bf[nt2][3]);
                }
            // pass B: Ql.Kh
#pragma unroll
            for (int mi = 0; mi < 2; mi++)
#pragma unroll
                for (int nt2 = 0; nt2 < 4; nt2++) {
                    mma_f16(S[mi][2 * nt2],     ql2[mi], bf[nt2][0], bf[nt2][2]);
                    mma_f16(S[mi][2 * nt2 + 1], ql2[mi], bf[nt2][1], bf[nt2][3]);
                }
            // reload K-lo, pass C: Qh.Kl
#pragma unroll
            for (int nt2 = 0; nt2 < 4; nt2++)
                ldm_x4(bf[nt2], cvta_s(bKl + (nt2 * 16 + fr) * FROW + kc * 16 + fc));
#pragma unroll
            for (int mi = 0; mi < 2; mi++)
#pragma unroll
                for (int nt2 = 0; nt2 < 4; nt2++) {
                    mma_f16(S[mi][2 * nt2],     qhF[mi][kc], bf[nt2][0], bf[nt2][2]);
                    mma_f16(S[mi][2 * nt2 + 1], qhF[mi][kc], bf[nt2][1], bf[nt2][3]);
                }
        }

        // ---- online softmax per m-tile (log2 domain, lazy rescale) ----
#pragma unroll
        for (int mi = 0; mi < 2; mi++) {
            float mx0 = S[mi][0][0], mx1 = S[mi][0][2];
#pragma unroll
            for (int nt = 0; nt < 8; nt++) {
                mx0 = fmaxf(mx0, fmaxf(S[mi][nt][0], S[mi][nt][1]));
                mx1 = fmaxf(mx1, fmaxf(S[mi][nt][2], S[mi][nt][3]));
            }
            mx0 = fmaxf(mx0, __shfl_xor_sync(0xffffffffu, mx0, 1));
            mx0 = fmaxf(mx0, __shfl_xor_sync(0xffffffffu, mx0, 2));
            mx1 = fmaxf(mx1, __shfl_xor_sync(0xffffffffu, mx1, 1));
            mx1 = fmaxf(mx1, __shfl_xor_sync(0xffffffffu, mx1, 2));
            float mn0 = fmaxf(m_[mi][0], mx0), mn1 = fmaxf(m_[mi][1], mx1);
            bool up0 = mn0 > m_[mi][0], up1 = mn1 > m_[mi][1];
            float c0 = up0 ? exp2f(m_[mi][0] - mn0) : 1.0f;
            float c1 = up1 ? exp2f(m_[mi][1] - mn1) : 1.0f;
            float s0 = 0.0f, s1 = 0.0f;
#pragma unroll
            for (int nt = 0; nt < 8; nt++) {
                S[mi][nt][0] = exp2f(S[mi][nt][0] - mn0); s0 += S[mi][nt][0];
                S[mi][nt][1] = exp2f(S[mi][nt][1] - mn0); s0 += S[mi][nt][1];
                S[mi][nt][2] = exp2f(S[mi][nt][2] - mn1); s1 += S[mi][nt][2];
                S[mi][nt][3] = exp2f(S[mi][nt][3] - mn1); s1 += S[mi][nt][3];
            }
            s0 += __shfl_xor_sync(0xffffffffu, s0, 1);
            s0 += __shfl_xor_sync(0xffffffffu, s0, 2);
            s1 += __shfl_xor_sync(0xffffffffu, s1, 1);
            s1 += __shfl_xor_sync(0xffffffffu, s1, 2);
            l_[mi][0] = l_[mi][0] * c0 + s0;
            l_[mi][1] = l_[mi][1] * c1 + s1;
            m_[mi][0] = mn0; m_[mi][1] = mn1;
            if (up0 || up1) {
#pragma unroll
                for (int dt = 0; dt < 8; dt++) {
                    O[mi][dt][0] *= c0; O[mi][dt][1] *= c0;
                    O[mi][dt][2] *= c1; O[mi][dt][3] *= c1;
                }
            }
        }

        // ---- O += P.V : V fragments shared across both m-tiles ----
#pragma unroll
        for (int kc = 0; kc < 4; kc++) {
            uint32_t a0[4], a1[4];
            a0[0] = pk2(S[0][2 * kc][0],     S[0][2 * kc][1]);
            a0[1] = pk2(S[0][2 * kc][2],     S[0][2 * kc][3]);
            a0[2] = pk2(S[0][2 * kc + 1][0], S[0][2 * kc + 1][1]);
            a0[3] = pk2(S[0][2 * kc + 1][2], S[0][2 * kc + 1][3]);
            a1[0] = pk2(S[1][2 * kc][0],     S[1][2 * kc][1]);
            a1[1] = pk2(S[1][2 * kc][2],     S[1][2 * kc][3]);
            a1[2] = pk2(S[1][2 * kc + 1][0], S[1][2 * kc + 1][1]);
            a1[3] = pk2(S[1][2 * kc + 1][2], S[1][2 * kc + 1][3]);
            int vrow = kc * 16 + fr;
#pragma unroll
            for (int dt2 = 0; dt2 < 4; dt2++) {
                uint32_t r[4];
                ldm_x4t(r, cvta_s(bV + vrow * FROW + dt2 * 16 + fc));
                mma_f16(O[0][2 * dt2],     a0, r[0], r[1]);
                mma_f16(O[0][2 * dt2 + 1], a0, r[2], r[3]);
                mma_f16(O[1][2 * dt2],     a1, r[0], r[1]);
                mma_f16(O[1][2 * dt2 + 1], a1, r[2], r[3]);
            }
        }
        __syncthreads();
    }

    // ---- write output ----
    int dcol = h * DHEAD + 2 * (lane & 3);
#pragma unroll
    for (int mi = 0; mi < 2; mi++) {
        float il0 = 1.0f / l_[mi][0], il1 = 1.0f / l_[mi][1];
        int row0 = b * SEQ + qt * 128 + 32 * w + 16 * mi + (lane >> 2);
#pragma unroll
        for (int dt = 0; dt < 8; dt++) {
            *(float2*)&Out[(size_t)row0 * DMODEL + dcol + dt * 8] =
                make_float2(O[mi][dt][0] * il0, O[mi][dt][1] * il0);
            *(float2*)&Out[(size_t)(row0 + 8) * DMODEL + dcol + dt * 8] =
                make_float2(O[mi][dt][2] * il1, O[mi][dt][3] * il1);
        }
    }
}

// =================================================================
extern "C" void kernel_launch(void* const* d_in, const int* in_sizes, int n_in,
                              void* d_out, int out_size)
{
    const float* q  = (const float*)d_in[0];
    const float* k  = (const float*)d_in[1];
    const float* v  = (const float*)d_in[2];
    const float* Wq = (const float*)d_in[3];
    const float* bq = (const float*)d_in[4];
    const float* Wk = (const float*)d_in[5];
    const float* bk = (const float*)d_in[6];
    const float* Wv = (const float*)d_in[7];
    const float* bv = (const float*)d_in[8];
    float* out = (float*)d_out;

    __half *Qh, *Ql, *Kh, *Kl, *Vv;
    cudaGetSymbolAddress((void**)&Qh, g_Qh);
    cudaGetSymbolAddress((void**)&Ql, g_Ql);
    cudaGetSymbolAddress((void**)&Kh, g_Kh);
    cudaGetSymbolAddress((void**)&Kl, g_Kl);
    cudaGetSymbolAddress((void**)&Vv, g_Vv);

    const int n4i = (int)(MD_ / 4);   // 1572864
    const int n4w = (int)(WD_ / 4);   // 147456

    {
        long long tot = 3LL * n4i + 3LL * n4w;
        int blocks = (int)((tot + 255) / 256);
        split6_bf16<<<blocks, 256>>>(q, k, v, Wq, Wk, Wv, n4i, n4w);
    }

    cudaFuncSetAttribute(proj_mma, cudaFuncAttributeMaxDynamicSharedMemorySize, PJ_SMEM);
    cudaFuncSetAttribute(flash_mma, cudaFuncAttributeMaxDynamicSharedMemorySize, FA_SMEM);

    dim3 pgrid(DMODEL / 128, MROWS / 128, 3);   // (6, 64, 3) — all 3 GEMMs
    proj_mma<<<pgrid, 256, PJ_SMEM>>>(bq, bk, bv);

    dim3 agrid(SEQ / 128, NHEAD, BS);           // (16, 12, 4)
    flash_mma<<<agrid, 128, FA_SMEM>>>(Qh, Ql, Kh, Kl, Vv, out);
}